// round 8
// baseline (speedup 1.0000x reference)
#include <cuda_runtime.h>
#include <cuda_bf16.h>

#define BB   32
#define TT   1024
#define DD   512
#define HH   512
#define G4   2048
#define NCTA 128

// ---------------- scratch (static device globals; no allocs allowed) --------
__device__ float    g_xw[(size_t)TT * BB * G4];   // [t][b][4H] precomputed x@Wx + bias
__device__ float    g_h[2][BB * HH];              // double-buffered hidden state, [b][j] layout
__device__ unsigned g_bar;                        // grid barrier counter

// ---------------- packed fp32x2 helpers -------------------------------------
__device__ __forceinline__ unsigned long long pack2(float x) {
    unsigned long long r;
    asm("mov.b64 %0, {%1, %1};" : "=l"(r) : "r"(__float_as_uint(x)));
    return r;
}
__device__ __forceinline__ void fma2(unsigned long long& acc, unsigned long long a, unsigned long long b) {
    asm("fma.rn.f32x2 %0, %1, %2, %0;" : "+l"(acc) : "l"(a), "l"(b));
}
__device__ __forceinline__ void add2(unsigned long long& acc, unsigned long long o) {
    asm("add.rn.f32x2 %0, %0, %1;" : "+l"(acc) : "l"(o));
}

__device__ __forceinline__ float fsig(float x) {
    return 1.f / (1.f + __expf(-x));
}
__device__ __forceinline__ float ftanh(float x) {
    float ax = fminf(fabsf(x), 15.f);
    float e  = __expf(2.f * ax);
    float r  = (e - 1.f) / (e + 1.f);
    return copysignf(r, x);
}

// ---------------- profiling pad (keeps ncu -s 5 aligned on lstm_rec) ---------
__global__ void pad_kernel() {}

// ---------------- reset: barrier counter + h buffer 0 -----------------------
__global__ void reset_kernel() {
    int idx = blockIdx.x * blockDim.x + threadIdx.x;
    if (idx == 0) g_bar = 0u;
    if (idx < BB * HH) g_h[0][idx] = 0.f;
}

// ---------------- kernel 1: XW = X @ Wx + b, stored [t][b][4H] ---------------
// 128x128 tile, 256 threads, 8x8 register tile, f32x2 FMA, swizzled Bs.
__global__ __launch_bounds__(256) void gemm_xw_kernel(
    const float* __restrict__ X, const float* __restrict__ Wx, const float* __restrict__ bias)
{
    __shared__ float As[16][132];   // transposed A tile [k][m], padded
    __shared__ float Bs[16][128];   // B tile [k][n], 16B-unit swizzled

    int tid = threadIdx.x;
    int m0 = blockIdx.y * 128;
    int n0 = blockIdx.x * 128;
    int ty = tid >> 4, tx = tid & 15;

    int u0 = tx * 2;
    int s0 = u0 ^ ((u0 >> 3) & 3);
    int u1 = u0 + 1;
    int s1 = u1 ^ ((u1 >> 3) & 3);

    unsigned long long acc[8][4];
#pragma unroll
    for (int i = 0; i < 8; i++)
#pragma unroll
        for (int j = 0; j < 4; j++) acc[i][j] = 0ull;

    for (int k0 = 0; k0 < DD; k0 += 16) {
#pragma unroll
        for (int i = 0; i < 2; i++) {          // A: transpose on store
            int f = tid + 256 * i;
            int r = f >> 2, cs = f & 3;
            float4 v = *(const float4*)&X[(size_t)(m0 + r) * DD + k0 + cs * 4];
            As[cs * 4 + 0][r] = v.x; As[cs * 4 + 1][r] = v.y;
            As[cs * 4 + 2][r] = v.z; As[cs * 4 + 3][r] = v.w;
        }
#pragma unroll
        for (int i = 0; i < 2; i++) {          // B: swizzled on store
            int f = tid + 256 * i;
            int r = f >> 5, cs = f & 31;
            int csw = cs ^ ((cs >> 3) & 3);
            *(float4*)&Bs[r][csw * 4] = *(const float4*)&Wx[(size_t)(k0 + r) * G4 + n0 + cs * 4];
        }
        __syncthreads();
#pragma unroll 4
        for (int kk = 0; kk < 16; kk++) {
            float4 a0 = *(float4*)&As[kk][ty * 8];
            float4 a1 = *(float4*)&As[kk][ty * 8 + 4];
            ulonglong2 w0 = *(ulonglong2*)&Bs[kk][s0 * 4];
            ulonglong2 w1 = *(ulonglong2*)&Bs[kk][s1 * 4];
            unsigned long long wp[4] = {w0.x, w0.y, w1.x, w1.y};
            float av[8] = {a0.x, a0.y, a0.z, a0.w, a1.x, a1.y, a1.z, a1.w};
#pragma unroll
            for (int bi = 0; bi < 8; bi++) {
                unsigned long long ad = pack2(av[bi]);
#pragma unroll
                for (int ci = 0; ci < 4; ci++) fma2(acc[bi][ci], ad, wp[ci]);
            }
        }
        __syncthreads();
    }

    float bl[8];
#pragma unroll
    for (int ci = 0; ci < 8; ci++) bl[ci] = bias[n0 + tx * 8 + ci];

#pragma unroll
    for (int bi = 0; bi < 8; bi++) {
        int m = m0 + ty * 8 + bi;
        int bb = m >> 10, t = m & 1023;       // m = b*T + t
        float* dst = &g_xw[((size_t)t * BB + bb) * G4 + n0 + tx * 8];
#pragma unroll
        for (int ci = 0; ci < 4; ci++) {
            unsigned long long u = acc[bi][ci];
            dst[ci * 2]     = __uint_as_float((unsigned)u)         + bl[ci * 2];
            dst[ci * 2 + 1] = __uint_as_float((unsigned)(u >> 32)) + bl[ci * 2 + 1];
        }
    }
}

// ---------------- kernel 2: persistent recurrence ----------------------------
// 128 CTAs x 256 threads; ~101KB smem -> 1 CTA/SM; 128 <= 148 SMs single wave.
// Thread (half, b, j): computes all 4 gate pre-activations for (b,j) over K-half
// via 2 packed f32x2 acc pairs -> one smem half-exchange -> SAME thread does the
// gate update (c in a register). No butterfly, no cross-warp reduce tree.
// h_s [b][k] stride 516 (conflict-free); loader warp == reader warp (cp.async,
// 2 commit groups, group g = k-offsets [128g, 128g+128) of the warp's k-half).
__global__ __launch_bounds__(256, 1) void lstm_rec_kernel(
    const float* __restrict__ Wh, float* __restrict__ out)
{
    extern __shared__ float smem[];
    float* wh_s = smem;                    // [512][16] = [k][j*4+gate], 32 KB
    float* h_s  = smem + 512 * 16;         // [32][516] padded, ~64.5 KB
    float* xch  = h_s + 32 * 516;          // [128][4]  2 KB half-exchange

    int tid = threadIdx.x;
    int j0  = blockIdx.x * 4;

    // Wh slice reordered: wh_s[k][j*4+g] = Wh[k][g*512 + j0 + j]
    for (int idx = tid; idx < 512 * 16; idx += 256) {
        int k = idx >> 4, c = idx & 15;
        int j = c >> 2, g = c & 3;
        wh_s[idx] = Wh[(size_t)k * G4 + g * HH + j0 + j];
    }

    int w    = tid >> 5;
    int lane = tid & 31;
    int half = tid >> 7;                   // 0/1 -> K halves [0,256) / [256,512)
    int bj   = tid & 127;
    int b    = bj >> 2, jj = bj & 3;
    int kbase = half * 256;

    // loader role: warp w loads h rows 8*(w&3)..+7, k-half (w>>2)*256..+255
    // (matches exactly the rows/k-half its own threads read: b = (tid&127)>>2)
    int lrow0 = (w & 3) * 8;
    int lk0   = (w >> 2) * 256;
    unsigned hs_base = (unsigned)__cvta_generic_to_shared(h_s);

    const float* hrow  = h_s + b * 516 + kbase;       // this thread's h slice
    const float* wbase = wh_s + jj * 4;

    float creg = 0.f;
    float* outp = out + ((size_t)b * TT) * HH + j0 + jj;

    unsigned bar_target = NCTA;
    __syncthreads();

    // px prefetch for t=0 (half0 threads = updaters)
    float px0 = 0.f, px1 = 0.f, px2 = 0.f, px3 = 0.f;
    if (half == 0) {
        const float* xr = g_xw + (size_t)b * G4 + j0 + jj;
        px0 = __ldg(xr);        px1 = __ldg(xr + 512);
        px2 = __ldg(xr + 1024); px3 = __ldg(xr + 1536);
    }

    for (int t = 0; t < TT; t++) {
        // per-warp h broadcast: 8 KB in 2 commit groups of 4 KB.
        // Group grp covers k-offsets [128*grp, 128*grp+128) of this warp's
        // 256-float k-half, for all 8 of its rows (8 iters x 32 lanes x 16B).
        {
            const float* src = g_h[t & 1];
#pragma unroll
            for (int grp = 0; grp < 2; grp++) {
#pragma unroll
                for (int i = 0; i < 8; i++) {
                    int uu  = i * 32 + lane;            // 0..255
                    int row = uu >> 5;                  // 8 rows, 32 units each
                    int cu  = (uu & 31) + grp * 32;     // 64 units (=256 floats) per row
                    int gr  = lrow0 + row;
                    int kk  = lk0 + cu * 4;
                    asm volatile("cp.async.cg.shared.global [%0], [%1], 16;"
                                 :: "r"(hs_base + (unsigned)((gr * 516 + kk) * 4)),
                                    "l"(src + (size_t)gr * HH + kk)
                                 : "memory");
                }
                asm volatile("cp.async.commit_group;");
            }
        }

        unsigned long long a01c0 = 0ull, a01c1 = 0ull, a23c0 = 0ull, a23c1 = 0ull;

#pragma unroll
        for (int r = 0; r < 2; r++) {
            if (r == 0) { asm volatile("cp.async.wait_group 1;" ::: "memory"); }
            else        { asm volatile("cp.async.wait_group 0;" ::: "memory"); }
            __syncwarp();
            int rb = r * 128;
#pragma unroll 4
            for (int kk = 0; kk < 64; kk += 4) {
                float4 h0 = *(const float4*)&hrow[rb + kk];
                float4 h1 = *(const float4*)&hrow[rb + 64 + kk];
                float hv0[4] = {h0.x, h0.y, h0.z, h0.w};
                float hv1[4] = {h1.x, h1.y, h1.z, h1.w};
#pragma unroll
                for (int u = 0; u < 4; u++) {
                    int k0 = kbase + rb + kk + u;
                    int k1 = k0 + 64;
                    ulonglong2 w0 = *(const ulonglong2*)&wbase[k0 * 16];
                    ulonglong2 w1 = *(const ulonglong2*)&wbase[k1 * 16];
                    unsigned long long hd0 = pack2(hv0[u]);
                    unsigned long long hd1 = pack2(hv1[u]);
                    fma2(a01c0, hd0, w0.x);
                    fma2(a23c0, hd0, w0.y);
                    fma2(a01c1, hd1, w1.x);
                    fma2(a23c1, hd1, w1.y);
                }
            }
        }

        unsigned long long z01 = a01c0; add2(z01, a01c1);
        unsigned long long z23 = a23c0; add2(z23, a23c1);

        if (half == 1) {   // publish upper-K partials
            *(unsigned long long*)&xch[bj * 4]     = z01;
            *(unsigned long long*)&xch[bj * 4 + 2] = z23;
        }
        __syncthreads();

        if (half == 0) {   // combine + gates + state update, all in one thread
            add2(z01, *(const unsigned long long*)&xch[bj * 4]);
            add2(z23, *(const unsigned long long*)&xch[bj * 4 + 2]);
            float zi = __uint_as_float((unsigned)z01)         + px0;
            float zf = __uint_as_float((unsigned)(z01 >> 32)) + px1;
            float zg = __uint_as_float((unsigned)z23)         + px2;
            float zo = __uint_as_float((unsigned)(z23 >> 32)) + px3;
            float ig = fsig(zi);
            float fg = fsig(zf);
            float gg = ftanh(zg);
            float og = fsig(zo);
            float cn = fg * creg + ig * gg;
            creg = cn;
            float hn = og * ftanh(cn);
            g_h[(t + 1) & 1][(size_t)b * HH + j0 + jj] = hn;
            outp[(size_t)t * HH] = hn;

            // prefetch next step's px under the barrier
            int tn = (t + 1 < TT) ? t + 1 : t;
            const float* xr = g_xw + ((size_t)tn * BB + b) * G4 + j0 + jj;
            px0 = __ldg(xr);        px1 = __ldg(xr + 512);
            px2 = __ldg(xr + 1024); px3 = __ldg(xr + 1536);
        }
        __syncthreads();

        if (tid == 0) {
            __threadfence();
            asm volatile("red.release.gpu.global.add.u32 [%0], %1;"
                         :: "l"(&g_bar), "r"(1u) : "memory");
            unsigned v;
            do {
                asm volatile("ld.acquire.gpu.global.u32 %0, [%1];"
                             : "=r"(v) : "l"(&g_bar) : "memory");
            } while (v < bar_target);
        }
        bar_target += NCTA;
        __syncthreads();
    }
}

// ---------------- kernel 3: gather final states ------------------------------
// lengths may be int64 (reference) or int32 (JAX w/o x64); sniff 128 valid bytes.
__global__ void gather_final_kernel(const int* __restrict__ lenraw, float* __restrict__ out) {
    __shared__ int is32;
    if (threadIdx.x == 0) {
        const long long* l64 = (const long long*)lenraw;
        int bad = 0;
        for (int b = 0; b < 16; b++) {
            long long v = l64[b];
            if (v < 0 || v > (long long)TT) bad = 1;
        }
        is32 = bad;
    }
    __syncthreads();
    int idx = blockIdx.x * blockDim.x + threadIdx.x;
    if (idx >= BB * HH) return;
    int b = idx >> 9, j = idx & 511;
    long long len = is32 ? (long long)lenraw[b] : ((const long long*)lenraw)[b];
    long long tt = len > 0 ? len - 1 : 0;
    out[(size_t)BB * TT * HH + idx] = out[((size_t)b * TT + tt) * HH + j];
}

// ---------------- launch ------------------------------------------------------
extern "C" void kernel_launch(void* const* d_in, const int* in_sizes, int n_in,
                              void* d_out, int out_size) {
    const float* X    = (const float*)d_in[0];
    const int*   lenr = (const int*)  d_in[1];
    const float* Wx   = (const float*)d_in[2];
    const float* Wh   = (const float*)d_in[3];
    const float* bias = (const float*)d_in[4];
    float* out = (float*)d_out;

    int smem_rec = (512 * 16 + 32 * 516 + 128 * 4) * 4;   // 100,864 B

    cudaFuncSetAttribute(lstm_rec_kernel,
                         cudaFuncAttributeMaxDynamicSharedMemorySize, smem_rec);
    cudaFuncSetAttribute(lstm_rec_kernel,
                         cudaFuncAttributePreferredSharedMemoryCarveout, 100);

    pad_kernel<<<1, 32>>>();                       // profile alignment only
    reset_kernel<<<64, 256>>>();
    gemm_xw_kernel<<<dim3(16, 256), 256>>>(X, Wx, bias);
    lstm_rec_kernel<<<NCTA, 256, smem_rec>>>(Wh, out);
    gather_final_kernel<<<64, 256>>>(lenr, out);
}

// round 10
// speedup vs baseline: 1.5924x; 1.5924x over previous
#include <cuda_runtime.h>
#include <cuda_bf16.h>

#define BB   32
#define TT   1024
#define DD   512
#define HH   512
#define G4   2048
#define NCTA 128

// ---------------- scratch (static device globals; no allocs allowed) --------
__device__ float    g_xw[(size_t)TT * BB * G4];   // [t][b][4H] precomputed x@Wx + bias
__device__ float    g_h[2][HH * BB];              // double-buffered hidden, [j][b] rows of 32
__device__ unsigned g_bar;                        // grid barrier counter

// ---------------- packed fp32x2 helpers -------------------------------------
__device__ __forceinline__ unsigned long long pack2(float x) {
    unsigned long long r;
    asm("mov.b64 %0, {%1, %1};" : "=l"(r) : "r"(__float_as_uint(x)));
    return r;
}
__device__ __forceinline__ void fma2(unsigned long long& acc, unsigned long long a, unsigned long long b) {
    asm("fma.rn.f32x2 %0, %1, %2, %0;" : "+l"(acc) : "l"(a), "l"(b));
}
__device__ __forceinline__ void add2(unsigned long long& acc, unsigned long long o) {
    asm("add.rn.f32x2 %0, %0, %1;" : "+l"(acc) : "l"(o));
}

__device__ __forceinline__ float fsig(float x) {
    return 1.f / (1.f + __expf(-x));
}
__device__ __forceinline__ float ftanh(float x) {
    float ax = fminf(fabsf(x), 15.f);
    float e  = __expf(2.f * ax);
    float r  = (e - 1.f) / (e + 1.f);
    return copysignf(r, x);
}

// ---------------- profiling pad (keeps ncu -s 5 aligned on lstm_rec) ---------
__global__ void pad_kernel() {}

// ---------------- reset: barrier counter + h buffer 0 -----------------------
__global__ void reset_kernel() {
    int idx = blockIdx.x * blockDim.x + threadIdx.x;
    if (idx == 0) g_bar = 0u;
    if (idx < HH * BB) g_h[0][idx] = 0.f;
}

// ---------------- kernel 1: XW = X @ Wx + b, stored [t][b][4H] ---------------
// (unchanged from best-passing R4 version)
__global__ __launch_bounds__(256) void gemm_xw_kernel(
    const float* __restrict__ X, const float* __restrict__ Wx, const float* __restrict__ bias)
{
    __shared__ float As[16][132];
    __shared__ float Bs[16][128];

    int tid = threadIdx.x;
    int m0 = blockIdx.y * 128;
    int n0 = blockIdx.x * 128;
    int ty = tid >> 4, tx = tid & 15;

    int u0 = tx * 2;
    int s0 = u0 ^ ((u0 >> 3) & 3);
    int u1 = u0 + 1;
    int s1 = u1 ^ ((u1 >> 3) & 3);

    unsigned long long acc[8][4];
#pragma unroll
    for (int i = 0; i < 8; i++)
#pragma unroll
        for (int j = 0; j < 4; j++) acc[i][j] = 0ull;

    for (int k0 = 0; k0 < DD; k0 += 16) {
#pragma unroll
        for (int i = 0; i < 2; i++) {
            int f = tid + 256 * i;
            int r = f >> 2, cs = f & 3;
            float4 v = *(const float4*)&X[(size_t)(m0 + r) * DD + k0 + cs * 4];
            As[cs * 4 + 0][r] = v.x; As[cs * 4 + 1][r] = v.y;
            As[cs * 4 + 2][r] = v.z; As[cs * 4 + 3][r] = v.w;
        }
#pragma unroll
        for (int i = 0; i < 2; i++) {
            int f = tid + 256 * i;
            int r = f >> 5, cs = f & 31;
            int csw = cs ^ ((cs >> 3) & 3);
            *(float4*)&Bs[r][csw * 4] = *(const float4*)&Wx[(size_t)(k0 + r) * G4 + n0 + cs * 4];
        }
        __syncthreads();
#pragma unroll 4
        for (int kk = 0; kk < 16; kk++) {
            float4 a0 = *(float4*)&As[kk][ty * 8];
            float4 a1 = *(float4*)&As[kk][ty * 8 + 4];
            ulonglong2 w0 = *(ulonglong2*)&Bs[kk][s0 * 4];
            ulonglong2 w1 = *(ulonglong2*)&Bs[kk][s1 * 4];
            unsigned long long wp[4] = {w0.x, w0.y, w1.x, w1.y};
            float av[8] = {a0.x, a0.y, a0.z, a0.w, a1.x, a1.y, a1.z, a1.w};
#pragma unroll
            for (int bi = 0; bi < 8; bi++) {
                unsigned long long ad = pack2(av[bi]);
#pragma unroll
                for (int ci = 0; ci < 4; ci++) fma2(acc[bi][ci], ad, wp[ci]);
            }
        }
        __syncthreads();
    }

    float bl[8];
#pragma unroll
    for (int ci = 0; ci < 8; ci++) bl[ci] = bias[n0 + tx * 8 + ci];

#pragma unroll
    for (int bi = 0; bi < 8; bi++) {
        int m = m0 + ty * 8 + bi;
        int bb = m >> 10, t = m & 1023;
        float* dst = &g_xw[((size_t)t * BB + bb) * G4 + n0 + tx * 8];
#pragma unroll
        for (int ci = 0; ci < 4; ci++) {
            unsigned long long u = acc[bi][ci];
            dst[ci * 2]     = __uint_as_float((unsigned)u)         + bl[ci * 2];
            dst[ci * 2 + 1] = __uint_as_float((unsigned)(u >> 32)) + bl[ci * 2 + 1];
        }
    }
}

// ---------------- kernel 2: persistent recurrence ----------------------------
// R4's high-ILP 8x8 split-K GEMM (32 f32x2 accumulators) + per-warp pipelined
// cp.async h-load (2 groups; thread k-set 64w+32h+8g+j overlaps load halves),
// swizzled h_s units, butterfly + padded red_s (stride 66), direct update-thread
// gather (no z_s stage), barrier without redundant threadfence.
__global__ __launch_bounds__(256, 1) void lstm_rec_kernel(
    const float* __restrict__ Wh, float* __restrict__ out)
{
    extern __shared__ float smem[];
    float* wh_s  = smem;                   // [512][16]  32 KB (c = gate*4 + jj)
    float* h_s   = smem + 512 * 16;        // [512][8 units of 16B] 64 KB, swizzled
    float* red_s = h_s + 512 * 8 * 4;      // [64][66]   ~17 KB

    int tid = threadIdx.x;
    int j0  = blockIdx.x * 4;

    // Wh slice: wh_s[k][c], c = gate*4 + jj
    for (int idx = tid; idx < 512 * 16; idx += 256) {
        int k = idx >> 4, c = idx & 15;
        wh_s[idx] = Wh[(size_t)k * G4 + (c >> 2) * HH + j0 + (c & 3)];
    }

    int w    = tid >> 5;
    int lane = tid & 31;
    int g    = (tid >> 3) & 3;
    int pos  = tid & 7;
    int b0   = (pos >> 1) * 8, c0 = (pos & 1) * 8;
    int buA  = (pos >> 1) * 2;             // first 16B h-unit (logical)
    int kw   = w * 64;                     // warp k-range [kw, kw+64)
    unsigned hs_base = (unsigned)__cvta_generic_to_shared(h_s);

    // update role (tid < 128): (batch ub, h-col j0+uj)
    int ub = tid >> 2, uj = tid & 3;
    float creg = 0.f;
    float* outp = out + ((size_t)ub * TT) * HH + j0 + uj;
    int p0 = (ub >> 3) << 1;
    int e0 = ((ub & 7) << 3) | uj;
    int e1 = e0 + 4;

    unsigned bar_target = NCTA;
    __syncthreads();

    float px0 = 0.f, px1 = 0.f, px2 = 0.f, px3 = 0.f;
    if (tid < 128) {
        const float* xr = g_xw + (size_t)ub * G4 + j0 + uj;
        px0 = __ldg(xr);        px1 = __ldg(xr + 512);
        px2 = __ldg(xr + 1024); px3 = __ldg(xr + 1536);
    }

    for (int t = 0; t < TT; t++) {
        // per-warp h load: 2 groups of 4KB; group grp = k in [kw+32*grp, +32)
        {
            const float* src = g_h[t & 1];
#pragma unroll
            for (int grp = 0; grp < 2; grp++) {
#pragma unroll
                for (int i = 0; i < 8; i++) {
                    int v  = i * 32 + lane;          // 0..255
                    int r  = v >> 3;                 // 0..31
                    int bu = v & 7;
                    int k  = kw + grp * 32 + r;
                    int s  = (k >> 3) & 7;
                    int us = bu ^ s;
                    asm volatile("cp.async.cg.shared.global [%0], [%1], 16;"
                                 :: "r"(hs_base + (unsigned)((k * 8 + us) * 16)),
                                    "l"(src + (size_t)k * 32 + bu * 4)
                                 : "memory");
                }
                asm volatile("cp.async.commit_group;");
            }
        }

        unsigned long long acc[8][4];
#pragma unroll
        for (int i = 0; i < 8; i++)
#pragma unroll
            for (int j = 0; j < 4; j++) acc[i][j] = 0ull;

#pragma unroll
        for (int hh = 0; hh < 2; hh++) {
            if (hh == 0) { asm volatile("cp.async.wait_group 1;" ::: "memory"); }
            else         { asm volatile("cp.async.wait_group 0;" ::: "memory"); }
            __syncwarp();
            int kh = kw + 32 * hh + 8 * g;
            int s8 = 4 * hh + g;
            int uA = buA ^ s8;
            int uB = (buA + 1) ^ s8;
#pragma unroll
            for (int j = 0; j < 8; j++) {
                int k = kh + j;
                float4 hA = *(float4*)&h_s[(k * 8 + uA) * 4];
                float4 hB = *(float4*)&h_s[(k * 8 + uB) * 4];
                ulonglong2 w0 = *(ulonglong2*)&wh_s[k * 16 + c0];
                ulonglong2 w1 = *(ulonglong2*)&wh_s[k * 16 + c0 + 4];
                unsigned long long wp[4] = {w0.x, w0.y, w1.x, w1.y};
                float hv[8] = {hA.x, hA.y, hA.z, hA.w, hB.x, hB.y, hB.z, hB.w};
#pragma unroll
                for (int bi = 0; bi < 8; bi++) {
                    unsigned long long ad = pack2(hv[bi]);
#pragma unroll
                    for (int ci = 0; ci < 4; ci++) fma2(acc[bi][ci], ad, wp[ci]);
                }
            }
        }

        // butterfly over the 4 lane-groups (lane bits 3,4)
#pragma unroll
        for (int bi = 0; bi < 8; bi++)
#pragma unroll
            for (int ci = 0; ci < 4; ci++) {
                unsigned long long v = acc[bi][ci];
                unsigned long long o = __shfl_xor_sync(0xffffffffu, v, 8);
                add2(v, o);
                o = __shfl_xor_sync(0xffffffffu, v, 16);
                add2(v, o);
                acc[bi][ci] = v;
            }

        if ((tid & 24) == 0) {   // g==0 lanes store the warp's 64-elem partial tile
            float* rb = red_s + (w * 8 + pos) * 66;
#pragma unroll
            for (int bi = 0; bi < 8; bi++)
#pragma unroll
                for (int ci = 0; ci < 4; ci++)
                    *(unsigned long long*)&rb[bi * 8 + ci * 2] = acc[bi][ci];
        }
        __syncthreads();

        // update threads gather their own 4 gates directly (no z_s stage)
        if (tid < 128) {
            float zi = 0.f, zf = 0.f, zg = 0.f, zo = 0.f;
#pragma unroll
            for (int w8 = 0; w8 < 8; w8++) {
                const float* rs0 = red_s + (w8 * 8 + p0) * 66;
                const float* rs1 = rs0 + 66;
                zi += rs0[e0];  zf += rs0[e1];
                zg += rs1[e0];  zo += rs1[e1];
            }
            zi += px0; zf += px1; zg += px2; zo += px3;
            float ig = fsig(zi);
            float fg = fsig(zf);
            float gg = ftanh(zg);
            float og = fsig(zo);
            float cn = fg * creg + ig * gg;
            creg = cn;
            float hn = og * ftanh(cn);
            g_h[(t + 1) & 1][(j0 + uj) * 32 + ub] = hn;
            outp[(size_t)t * HH] = hn;

            // prefetch next step's px under the barrier
            int tn = (t + 1 < TT) ? t + 1 : t;
            const float* xr = g_xw + ((size_t)tn * BB + ub) * G4 + j0 + uj;
            px0 = __ldg(xr);        px1 = __ldg(xr + 512);
            px2 = __ldg(xr + 1024); px3 = __ldg(xr + 1536);
        }
        __syncthreads();

        // grid barrier: syncthreads + release-arrive + acquire-spin (CG pattern)
        if (tid == 0) {
            asm volatile("red.release.gpu.global.add.u32 [%0], %1;"
                         :: "l"(&g_bar), "r"(1u) : "memory");
            unsigned v;
            do {
                asm volatile("ld.acquire.gpu.global.u32 %0, [%1];"
                             : "=r"(v) : "l"(&g_bar) : "memory");
            } while (v < bar_target);
        }
        bar_target += NCTA;
        __syncthreads();
    }
}

// ---------------- kernel 3: gather final states ------------------------------
__global__ void gather_final_kernel(const int* __restrict__ lenraw, float* __restrict__ out) {
    __shared__ int is32;
    if (threadIdx.x == 0) {
        const long long* l64 = (const long long*)lenraw;
        int bad = 0;
        for (int b = 0; b < 16; b++) {
            long long v = l64[b];
            if (v < 0 || v > (long long)TT) bad = 1;
        }
        is32 = bad;
    }
    __syncthreads();
    int idx = blockIdx.x * blockDim.x + threadIdx.x;
    if (idx >= BB * HH) return;
    int b = idx >> 9, j = idx & 511;
    long long len = is32 ? (long long)lenraw[b] : ((const long long*)lenraw)[b];
    long long tt = len > 0 ? len - 1 : 0;
    out[(size_t)BB * TT * HH + idx] = out[((size_t)b * TT + tt) * HH + j];
}

// ---------------- launch ------------------------------------------------------
extern "C" void kernel_launch(void* const* d_in, const int* in_sizes, int n_in,
                              void* d_out, int out_size) {
    const float* X    = (const float*)d_in[0];
    const int*   lenr = (const int*)  d_in[1];
    const float* Wx   = (const float*)d_in[2];
    const float* Wh   = (const float*)d_in[3];
    const float* bias = (const float*)d_in[4];
    float* out = (float*)d_out;

    int smem_rec = (512 * 16 + 512 * 8 * 4 + 64 * 66) * 4;   // 115,200 B

    cudaFuncSetAttribute(lstm_rec_kernel,
                         cudaFuncAttributeMaxDynamicSharedMemorySize, smem_rec);
    cudaFuncSetAttribute(lstm_rec_kernel,
                         cudaFuncAttributePreferredSharedMemoryCarveout, 100);

    pad_kernel<<<1, 32>>>();                       // profile alignment only
    reset_kernel<<<64, 256>>>();
    gemm_xw_kernel<<<dim3(16, 256), 256>>>(X, Wx, bias);
    lstm_rec_kernel<<<NCTA, 256, smem_rec>>>(Wh, out);
    gather_final_kernel<<<64, 256>>>(lenr, out);
}

// round 12
// speedup vs baseline: 1.8259x; 1.1466x over previous
#include <cuda_runtime.h>
#include <cuda_bf16.h>

#define BB   32
#define TT   1024
#define DD   512
#define HH   512
#define G4   2048
#define NCTA 128

// ---------------- scratch (static device globals; no allocs allowed) --------
__device__ float    g_xw[(size_t)TT * BB * G4];   // [t][b][4H] precomputed x@Wx + bias
__device__ float    g_h[2][HH * BB];              // double-buffered hidden, [j][b] rows of 32
__device__ unsigned g_bar;                        // grid barrier counter
__device__ __nv_bfloat16 g_xhi[(size_t)TT * BB * DD];  // X split-high, [m][k]
__device__ __nv_bfloat16 g_xlo[(size_t)TT * BB * DD];  // X split-low
__device__ __nv_bfloat16 g_whiT[(size_t)G4 * DD];      // Wx^T split-high, [n][k]
__device__ __nv_bfloat16 g_wloT[(size_t)G4 * DD];      // Wx^T split-low

// ---------------- packed fp32x2 helpers -------------------------------------
__device__ __forceinline__ unsigned long long pack2(float x) {
    unsigned long long r;
    asm("mov.b64 %0, {%1, %1};" : "=l"(r) : "r"(__float_as_uint(x)));
    return r;
}
__device__ __forceinline__ void fma2(unsigned long long& acc, unsigned long long a, unsigned long long b) {
    asm("fma.rn.f32x2 %0, %1, %2, %0;" : "+l"(acc) : "l"(a), "l"(b));
}
__device__ __forceinline__ void add2(unsigned long long& acc, unsigned long long o) {
    asm("add.rn.f32x2 %0, %0, %1;" : "+l"(acc) : "l"(o));
}

__device__ __forceinline__ float fsig(float x) {
    return 1.f / (1.f + __expf(-x));
}
__device__ __forceinline__ float ftanh(float x) {
    float ax = fminf(fabsf(x), 15.f);
    float e  = __expf(2.f * ax);
    float r  = (e - 1.f) / (e + 1.f);
    return copysignf(r, x);
}

// ---------------- tensor-core helpers ----------------------------------------
__device__ __forceinline__ void ldm4(unsigned* r, unsigned addr) {
    asm volatile("ldmatrix.sync.aligned.m8n8.x4.shared.b16 {%0,%1,%2,%3}, [%4];"
                 : "=r"(r[0]), "=r"(r[1]), "=r"(r[2]), "=r"(r[3]) : "r"(addr));
}
__device__ __forceinline__ void mma_bf16(float* c, const unsigned* a, const unsigned* b) {
    asm volatile(
        "mma.sync.aligned.m16n8k16.row.col.f32.bf16.bf16.f32 "
        "{%0,%1,%2,%3}, {%4,%5,%6,%7}, {%8,%9}, {%0,%1,%2,%3};"
        : "+f"(c[0]), "+f"(c[1]), "+f"(c[2]), "+f"(c[3])
        : "r"(a[0]), "r"(a[1]), "r"(a[2]), "r"(a[3]), "r"(b[0]), "r"(b[1]));
}

// ---------------- profiling pad ----------------------------------------------
__global__ void pad_kernel() {}

// ---------------- reset: barrier counter + h buffer 0 -----------------------
__global__ void reset_kernel() {
    int idx = blockIdx.x * blockDim.x + threadIdx.x;
    if (idx == 0) g_bar = 0u;
    if (idx < HH * BB) g_h[0][idx] = 0.f;
}

// ---------------- conversion kernels -----------------------------------------
__global__ void conv_x_kernel(const float* __restrict__ X) {
    size_t i = ((size_t)blockIdx.x * blockDim.x + threadIdx.x) * 4;
    if (i >= (size_t)TT * BB * DD) return;
    float4 v = *(const float4*)(X + i);
    __nv_bfloat16 h[4], l[4];
    float vv[4] = {v.x, v.y, v.z, v.w};
#pragma unroll
    for (int q = 0; q < 4; q++) {
        h[q] = __float2bfloat16(vv[q]);
        l[q] = __float2bfloat16(vv[q] - __bfloat162float(h[q]));
    }
    *(uint2*)(g_xhi + i) = *(uint2*)h;
    *(uint2*)(g_xlo + i) = *(uint2*)l;
}

__global__ void conv_w_kernel(const float* __restrict__ Wx) {
    int idx = blockIdx.x * blockDim.x + threadIdx.x;
    if (idx >= DD * G4) return;
    int k = idx >> 11, n = idx & (G4 - 1);
    float w = Wx[idx];
    __nv_bfloat16 hi = __float2bfloat16(w);
    __nv_bfloat16 lo = __float2bfloat16(w - __bfloat162float(hi));
    g_whiT[(size_t)n * DD + k] = hi;
    g_wloT[(size_t)n * DD + k] = lo;
}

// ---------------- kernel 1: XW via bf16-split tensor cores -------------------
// CTA 128x128, k16 stages x32, 2-stage cp.async pipeline.
// smem per stage: 4 arrays (Ahi,Alo,Bhi,Blo) of 128 rows x 48B (16 bf16 + pad).
// z = xhi*whi + xhi*wlo + xlo*whi  (3 mma into same fp32 frags).
#define XW_STAGE 24576
#define XW_ROWP  48
__global__ __launch_bounds__(256) void gemm_xw_tc_kernel(const float* __restrict__ bias) {
    extern __shared__ char xsmem[];
    unsigned sbase = (unsigned)__cvta_generic_to_shared(xsmem);

    int tid  = threadIdx.x;
    int lane = tid & 31;
    int w    = tid >> 5;
    int wm   = w >> 1, wn = w & 1;
    int m0   = blockIdx.y * 128;
    int n0   = blockIdx.x * 128;
    int g    = lane >> 2, tig = lane & 3;

    const __nv_bfloat16* srcs[4] = {
        g_xhi + (size_t)m0 * DD, g_xlo + (size_t)m0 * DD,
        g_whiT + (size_t)n0 * DD, g_wloT + (size_t)n0 * DD };

    float acc[2][8][4];
#pragma unroll
    for (int mt = 0; mt < 2; mt++)
#pragma unroll
        for (int f = 0; f < 8; f++)
#pragma unroll
            for (int q = 0; q < 4; q++) acc[mt][f][q] = 0.f;

    // cp.async one k16 stage (all 4 arrays, 128 rows each)
    auto load_stage = [&](int s, int kk) {
#pragma unroll
        for (int it = 0; it < 2; it++) {
            int task = tid + 256 * it;
            int arr  = task >> 7, row = task & 127;
            const __nv_bfloat16* src = srcs[arr] + (size_t)row * DD + kk;
            unsigned dst = sbase + (s & 1) * XW_STAGE + arr * 6144 + row * XW_ROWP;
            asm volatile("cp.async.cg.shared.global [%0], [%1], 16;"
                         :: "r"(dst), "l"(src) : "memory");
            asm volatile("cp.async.cg.shared.global [%0], [%1], 16;"
                         :: "r"(dst + 16), "l"(src + 8) : "memory");
        }
        asm volatile("cp.async.commit_group;");
    };

    load_stage(0, 0);

    // ldmatrix lane addressing (A and B share the same row-major tile pattern)
    int a_row_off = ((lane >> 3) & 1) * 8 + (lane & 7);
    int a_k_off   = ((lane >> 4) & 1) * 16;
    int b_row_off = ((lane >> 4) & 1) * 8 + (lane & 7);
    int b_k_off   = ((lane >> 3) & 1) * 16;

    for (int s = 0; s < 32; s++) {
        if (s + 1 < 32) load_stage(s + 1, (s + 1) * 16);
        if (s + 1 < 32) { asm volatile("cp.async.wait_group 1;" ::: "memory"); }
        else            { asm volatile("cp.async.wait_group 0;" ::: "memory"); }
        __syncthreads();

        unsigned st = sbase + (s & 1) * XW_STAGE;
        unsigned ah[2][4], al[2][4], bh[8][2], bl8[8][2];
#pragma unroll
        for (int mt = 0; mt < 2; mt++) {
            unsigned rowb = (wm * 32 + mt * 16 + a_row_off) * XW_ROWP + a_k_off;
            ldm4(ah[mt], st + 0    + rowb);
            ldm4(al[mt], st + 6144 + rowb);
        }
#pragma unroll
        for (int fp = 0; fp < 4; fp++) {
            unsigned rowb = (wn * 64 + fp * 16 + b_row_off) * XW_ROWP + b_k_off;
            unsigned r4[4];
            ldm4(r4, st + 12288 + rowb);
            bh[fp * 2][0] = r4[0];  bh[fp * 2][1] = r4[1];
            bh[fp * 2 + 1][0] = r4[2];  bh[fp * 2 + 1][1] = r4[3];
            ldm4(r4, st + 18432 + rowb);
            bl8[fp * 2][0] = r4[0];  bl8[fp * 2][1] = r4[1];
            bl8[fp * 2 + 1][0] = r4[2];  bl8[fp * 2 + 1][1] = r4[3];
        }
#pragma unroll
        for (int mt = 0; mt < 2; mt++)
#pragma unroll
            for (int f = 0; f < 8; f++) {
                mma_bf16(acc[mt][f], ah[mt], bh[f]);
                mma_bf16(acc[mt][f], ah[mt], bl8[f]);
                mma_bf16(acc[mt][f], al[mt], bh[f]);
            }
        __syncthreads();
    }

    // epilogue: + bias, scatter to g_xw[t][b][4H]
#pragma unroll
    for (int f = 0; f < 8; f++) {
        int col = n0 + wn * 64 + f * 8 + tig * 2;
        float bl0 = bias[col], bl1 = bias[col + 1];
#pragma unroll
        for (int mt = 0; mt < 2; mt++) {
            int mr0 = m0 + wm * 32 + mt * 16 + g;
            int bb = mr0 >> 10, t = mr0 & 1023;
            float2 v0 = {acc[mt][f][0] + bl0, acc[mt][f][1] + bl1};
            *(float2*)&g_xw[((size_t)t * BB + bb) * G4 + col] = v0;
            int mr1 = mr0 + 8;
            bb = mr1 >> 10; t = mr1 & 1023;
            float2 v1 = {acc[mt][f][2] + bl0, acc[mt][f][3] + bl1};
            *(float2*)&g_xw[((size_t)t * BB + bb) * G4 + col] = v1;
        }
    }
}

// ---------------- kernel 2: persistent recurrence (byte-identical to R10) ----
__global__ __launch_bounds__(256, 1) void lstm_rec_kernel(
    const float* __restrict__ Wh, float* __restrict__ out)
{
    extern __shared__ float smem[];
    float* wh_s  = smem;                   // [512][16]  32 KB (c = gate*4 + jj)
    float* h_s   = smem + 512 * 16;        // [512][8 units of 16B] 64 KB, swizzled
    float* red_s = h_s + 512 * 8 * 4;      // [64][66]   ~17 KB

    int tid = threadIdx.x;
    int j0  = blockIdx.x * 4;

    for (int idx = tid; idx < 512 * 16; idx += 256) {
        int k = idx >> 4, c = idx & 15;
        wh_s[idx] = Wh[(size_t)k * G4 + (c >> 2) * HH + j0 + (c & 3)];
    }

    int w    = tid >> 5;
    int lane = tid & 31;
    int g    = (tid >> 3) & 3;
    int pos  = tid & 7;
    int b0   = (pos >> 1) * 8, c0 = (pos & 1) * 8;
    int buA  = (pos >> 1) * 2;
    int kw   = w * 64;
    unsigned hs_base = (unsigned)__cvta_generic_to_shared(h_s);

    int ub = tid >> 2, uj = tid & 3;
    float creg = 0.f;
    float* outp = out + ((size_t)ub * TT) * HH + j0 + uj;
    int p0 = (ub >> 3) << 1;
    int e0 = ((ub & 7) << 3) | uj;
    int e1 = e0 + 4;

    unsigned bar_target = NCTA;
    __syncthreads();

    float px0 = 0.f, px1 = 0.f, px2 = 0.f, px3 = 0.f;
    if (tid < 128) {
        const float* xr = g_xw + (size_t)ub * G4 + j0 + uj;
        px0 = __ldg(xr);        px1 = __ldg(xr + 512);
        px2 = __ldg(xr + 1024); px3 = __ldg(xr + 1536);
    }

    for (int t = 0; t < TT; t++) {
        {
            const float* src = g_h[t & 1];
#pragma unroll
            for (int grp = 0; grp < 2; grp++) {
#pragma unroll
                for (int i = 0; i < 8; i++) {
                    int v  = i * 32 + lane;
                    int r  = v >> 3;
                    int bu = v & 7;
                    int k  = kw + grp * 32 + r;
                    int s  = (k >> 3) & 7;
                    int us = bu ^ s;
                    asm volatile("cp.async.cg.shared.global [%0], [%1], 16;"
                                 :: "r"(hs_base + (unsigned)((k * 8 + us) * 16)),
                                    "l"(src + (size_t)k * 32 + bu * 4)
                                 : "memory");
                }
                asm volatile("cp.async.commit_group;");
            }
        }

        unsigned long long acc[8][4];
#pragma unroll
        for (int i = 0; i < 8; i++)
#pragma unroll
            for (int j = 0; j < 4; j++) acc[i][j] = 0ull;

#pragma unroll
        for (int hh = 0; hh < 2; hh++) {
            if (hh == 0) { asm volatile("cp.async.wait_group 1;" ::: "memory"); }
            else         { asm volatile("cp.async.wait_group 0;" ::: "memory"); }
            __syncwarp();
            int kh = kw + 32 * hh + 8 * g;
            int s8 = 4 * hh + g;
            int uA = buA ^ s8;
            int uB = (buA + 1) ^ s8;
#pragma unroll
            for (int j = 0; j < 8; j++) {
                int k = kh + j;
                float4 hA = *(float4*)&h_s[(k * 8 + uA) * 4];
                float4 hB = *(float4*)&h_s[(k * 8 + uB) * 4];
                ulonglong2 w0 = *(ulonglong2*)&wh_s[k * 16 + c0];
                ulonglong2 w1 = *(ulonglong2*)&wh_s[k * 16 + c0 + 4];
                unsigned long long wp[4] = {w0.x, w0.y, w1.x, w1.y};
                float hv[8] = {hA.x, hA.y, hA.z, hA.w, hB.x, hB.y, hB.z, hB.w};
#pragma unroll
                for (int bi = 0; bi < 8; bi++) {
                    unsigned long long ad = pack2(hv[bi]);
#pragma unroll
                    for (int ci = 0; ci < 4; ci++) fma2(acc[bi][ci], ad, wp[ci]);
                }
            }
        }

#pragma unroll
        for (int bi = 0; bi < 8; bi++)
#pragma unroll
            for (int ci = 0; ci < 4; ci++) {
                unsigned long long v = acc[bi][ci];
                unsigned long long o = __shfl_xor_sync(0xffffffffu, v, 8);
                add2(v, o);
                o = __shfl_xor_sync(0xffffffffu, v, 16);
                add2(v, o);
                acc[bi][ci] = v;
            }

        if ((tid & 24) == 0) {
            float* rb = red_s + (w * 8 + pos) * 66;
#pragma unroll
            for (int bi = 0; bi < 8; bi++)
#pragma unroll
                for (int ci = 0; ci < 4; ci++)
                    *(unsigned long long*)&rb[bi * 8 + ci * 2] = acc[bi][ci];
        }
        __syncthreads();

        if (tid < 128) {
            float zi = 0.f, zf = 0.f, zg = 0.f, zo = 0.f;
#pragma unroll
            for (int w8 = 0; w8 < 8; w8++) {
                const float* rs0 = red_s + (w8 * 8 + p0) * 66;
                const float* rs1 = rs0 + 66;
                zi += rs0[e0];  zf += rs0[e1];
                zg += rs1[e0];  zo += rs1[e1];
            }
            zi += px0; zf += px1; zg += px2; zo += px3;
            float ig = fsig(zi);
            float fg = fsig(zf);
            float gg = ftanh(zg);
            float og = fsig(zo);
            float cn = fg * creg + ig * gg;
            creg = cn;
            float hn = og * ftanh(cn);
            g_h[(t + 1) & 1][(j0 + uj) * 32 + ub] = hn;
            outp[(size_t)t * HH] = hn;

            int tn = (t + 1 < TT) ? t + 1 : t;
            const float* xr = g_xw + ((size_t)tn * BB + ub) * G4 + j0 + uj;
            px0 = __ldg(xr);        px1 = __ldg(xr + 512);
            px2 = __ldg(xr + 1024); px3 = __ldg(xr + 1536);
        }
        __syncthreads();

        if (tid == 0) {
            asm volatile("red.release.gpu.global.add.u32 [%0], %1;"
                         :: "l"(&g_bar), "r"(1u) : "memory");
            unsigned v;
            do {
                asm volatile("ld.acquire.gpu.global.u32 %0, [%1];"
                             : "=r"(v) : "l"(&g_bar) : "memory");
            } while (v < bar_target);
        }
        bar_target += NCTA;
        __syncthreads();
    }
}

// ---------------- kernel 3: gather final states ------------------------------
__global__ void gather_final_kernel(const int* __restrict__ lenraw, float* __restrict__ out) {
    __shared__ int is32;
    if (threadIdx.x == 0) {
        const long long* l64 = (const long long*)lenraw;
        int bad = 0;
        for (int b = 0; b < 16; b++) {
            long long v = l64[b];
            if (v < 0 || v > (long long)TT) bad = 1;
        }
        is32 = bad;
    }
    __syncthreads();
    int idx = blockIdx.x * blockDim.x + threadIdx.x;
    if (idx >= BB * HH) return;
    int b = idx >> 9, j = idx & 511;
    long long len = is32 ? (long long)lenraw[b] : ((const long long*)lenraw)[b];
    long long tt = len > 0 ? len - 1 : 0;
    out[(size_t)BB * TT * HH + idx] = out[((size_t)b * TT + tt) * HH + j];
}

// ---------------- launch ------------------------------------------------------
extern "C" void kernel_launch(void* const* d_in, const int* in_sizes, int n_in,
                              void* d_out, int out_size) {
    const float* X    = (const float*)d_in[0];
    const int*   lenr = (const int*)  d_in[1];
    const float* Wx   = (const float*)d_in[2];
    const float* Wh   = (const float*)d_in[3];
    const float* bias = (const float*)d_in[4];
    float* out = (float*)d_out;

    int smem_rec = (512 * 16 + 512 * 8 * 4 + 64 * 66) * 4;   // 115,200 B
    int smem_xw  = 2 * XW_STAGE;                              // 49,152 B

    cudaFuncSetAttribute(lstm_rec_kernel,
                         cudaFuncAttributeMaxDynamicSharedMemorySize, smem_rec);
    cudaFuncSetAttribute(lstm_rec_kernel,
                         cudaFuncAttributePreferredSharedMemoryCarveout, 100);
    cudaFuncSetAttribute(gemm_xw_tc_kernel,
                         cudaFuncAttributeMaxDynamicSharedMemorySize, smem_xw);

    pad_kernel<<<1, 32>>>();                       // profile alignment only
    reset_kernel<<<64, 256>>>();
    conv_x_kernel<<<16384, 256>>>(X);
    conv_w_kernel<<<4096, 256>>>(Wx);
    gemm_xw_tc_kernel<<<dim3(16, 256), 256, smem_xw>>>(bias);
    lstm_rec_kernel<<<NCTA, 256, smem_rec>>>(Wh, out);
    gather_final_kernel<<<64, 256>>>(lenr, out);
}

// round 15
// speedup vs baseline: 1.8699x; 1.0241x over previous
#include <cuda_runtime.h>
#include <cuda_bf16.h>

#define BB   32
#define TT   1024
#define DD   512
#define HH   512
#define G4   2048
#define NCTA 128

// ---------------- scratch (static device globals; no allocs allowed) --------
__device__ float    g_xw[(size_t)TT * BB * G4];   // [t][b][4H] precomputed x@Wx + bias
__device__ __nv_bfloat16 g_hhi[2][BB * HH];       // hidden state split-high, [b][j]
__device__ __nv_bfloat16 g_hlo[2][BB * HH];       // hidden state split-low
__device__ unsigned g_bar;                        // grid barrier counter
__device__ __nv_bfloat16 g_xhi[(size_t)TT * BB * DD];  // X split-high, [m][k]
__device__ __nv_bfloat16 g_xlo[(size_t)TT * BB * DD];  // X split-low
__device__ __nv_bfloat16 g_whiT[(size_t)G4 * DD];      // Wx^T split-high, [n][k]
__device__ __nv_bfloat16 g_wloT[(size_t)G4 * DD];      // Wx^T split-low

__device__ __forceinline__ float fsig(float x) {
    return 1.f / (1.f + __expf(-x));
}
__device__ __forceinline__ float ftanh(float x) {
    float ax = fminf(fabsf(x), 15.f);
    float e  = __expf(2.f * ax);
    float r  = (e - 1.f) / (e + 1.f);
    return copysignf(r, x);
}

// ---------------- tensor-core helpers ----------------------------------------
__device__ __forceinline__ void ldm4(unsigned* r, unsigned addr) {
    asm volatile("ldmatrix.sync.aligned.m8n8.x4.shared.b16 {%0,%1,%2,%3}, [%4];"
                 : "=r"(r[0]), "=r"(r[1]), "=r"(r[2]), "=r"(r[3]) : "r"(addr));
}
__device__ __forceinline__ void mma_bf16(float* c, const unsigned* a, const unsigned* b) {
    asm volatile(
        "mma.sync.aligned.m16n8k16.row.col.f32.bf16.bf16.f32 "
        "{%0,%1,%2,%3}, {%4,%5,%6,%7}, {%8,%9}, {%0,%1,%2,%3};"
        : "+f"(c[0]), "+f"(c[1]), "+f"(c[2]), "+f"(c[3])
        : "r"(a[0]), "r"(a[1]), "r"(a[2]), "r"(a[3]), "r"(b[0]), "r"(b[1]));
}

// ---------------- reset: barrier counter + h buffer 0 -----------------------
__global__ void reset_kernel() {
    int idx = blockIdx.x * blockDim.x + threadIdx.x;
    if (idx == 0) g_bar = 0u;
    if (idx < (BB * HH) / 2) {
        ((unsigned*)g_hhi)[idx] = 0u;     // buffer 0 of both splits
        ((unsigned*)g_hlo)[idx] = 0u;
    }
}

// ---------------- conversion: X and Wx splits in one kernel ------------------
__global__ void conv_all_kernel(const float* __restrict__ X, const float* __restrict__ Wx) {
    if (blockIdx.x < 16384) {
        size_t i = ((size_t)blockIdx.x * 256 + threadIdx.x) * 4;
        if (i >= (size_t)TT * BB * DD) return;
        float4 v = *(const float4*)(X + i);
        __nv_bfloat16 h[4], l[4];
        float vv[4] = {v.x, v.y, v.z, v.w};
#pragma unroll
        for (int q = 0; q < 4; q++) {
            h[q] = __float2bfloat16(vv[q]);
            l[q] = __float2bfloat16(vv[q] - __bfloat162float(h[q]));
        }
        *(uint2*)(g_xhi + i) = *(uint2*)h;
        *(uint2*)(g_xlo + i) = *(uint2*)l;
    } else {
        int idx = (blockIdx.x - 16384) * 256 + threadIdx.x;
        if (idx >= DD * G4) return;
        int k = idx >> 11, n = idx & (G4 - 1);
        float w = Wx[idx];
        __nv_bfloat16 hi = __float2bfloat16(w);
        __nv_bfloat16 lo = __float2bfloat16(w - __bfloat162float(hi));
        g_whiT[(size_t)n * DD + k] = hi;
        g_wloT[(size_t)n * DD + k] = lo;
    }
}

// ---------------- kernel 1: XW via bf16-split tensor cores (R12, validated) --
#define XW_STAGE 24576
#define XW_ROWP  48
__global__ __launch_bounds__(256) void gemm_xw_tc_kernel(const float* __restrict__ bias) {
    extern __shared__ char xsmem[];
    unsigned sbase = (unsigned)__cvta_generic_to_shared(xsmem);

    int tid  = threadIdx.x;
    int lane = tid & 31;
    int w    = tid >> 5;
    int wm   = w >> 1, wn = w & 1;
    int m0   = blockIdx.y * 128;
    int n0   = blockIdx.x * 128;
    int g    = lane >> 2, tig = lane & 3;

    const __nv_bfloat16* srcs[4] = {
        g_xhi + (size_t)m0 * DD, g_xlo + (size_t)m0 * DD,
        g_whiT + (size_t)n0 * DD, g_wloT + (size_t)n0 * DD };

    float acc[2][8][4];
#pragma unroll
    for (int mt = 0; mt < 2; mt++)
#pragma unroll
        for (int f = 0; f < 8; f++)
#pragma unroll
            for (int q = 0; q < 4; q++) acc[mt][f][q] = 0.f;

    auto load_stage = [&](int s, int kk) {
#pragma unroll
        for (int it = 0; it < 2; it++) {
            int task = tid + 256 * it;
            int arr  = task >> 7, row = task & 127;
            const __nv_bfloat16* src = srcs[arr] + (size_t)row * DD + kk;
            unsigned dst = sbase + (s & 1) * XW_STAGE + arr * 6144 + row * XW_ROWP;
            asm volatile("cp.async.cg.shared.global [%0], [%1], 16;"
                         :: "r"(dst), "l"(src) : "memory");
            asm volatile("cp.async.cg.shared.global [%0], [%1], 16;"
                         :: "r"(dst + 16), "l"(src + 8) : "memory");
        }
        asm volatile("cp.async.commit_group;");
    };

    load_stage(0, 0);

    int a_row_off = ((lane >> 3) & 1) * 8 + (lane & 7);
    int a_k_off   = ((lane >> 4) & 1) * 16;
    int b_row_off = ((lane >> 4) & 1) * 8 + (lane & 7);
    int b_k_off   = ((lane >> 3) & 1) * 16;

    for (int s = 0; s < 32; s++) {
        if (s + 1 < 32) load_stage(s + 1, (s + 1) * 16);
        if (s + 1 < 32) { asm volatile("cp.async.wait_group 1;" ::: "memory"); }
        else            { asm volatile("cp.async.wait_group 0;" ::: "memory"); }
        __syncthreads();

        unsigned st = sbase + (s & 1) * XW_STAGE;
        unsigned ah[2][4], al[2][4], bh[8][2], bl8[8][2];
#pragma unroll
        for (int mt = 0; mt < 2; mt++) {
            unsigned rowb = (wm * 32 + mt * 16 + a_row_off) * XW_ROWP + a_k_off;
            ldm4(ah[mt], st + 0    + rowb);
            ldm4(al[mt], st + 6144 + rowb);
        }
#pragma unroll
        for (int fp = 0; fp < 4; fp++) {
            unsigned rowb = (wn * 64 + fp * 16 + b_row_off) * XW_ROWP + b_k_off;
            unsigned r4[4];
            ldm4(r4, st + 12288 + rowb);
            bh[fp * 2][0] = r4[0];  bh[fp * 2][1] = r4[1];
            bh[fp * 2 + 1][0] = r4[2];  bh[fp * 2 + 1][1] = r4[3];
            ldm4(r4, st + 18432 + rowb);
            bl8[fp * 2][0] = r4[0];  bl8[fp * 2][1] = r4[1];
            bl8[fp * 2 + 1][0] = r4[2];  bl8[fp * 2 + 1][1] = r4[3];
        }
#pragma unroll
        for (int mt = 0; mt < 2; mt++)
#pragma unroll
            for (int f = 0; f < 8; f++) {
                mma_bf16(acc[mt][f], ah[mt], bh[f]);
                mma_bf16(acc[mt][f], ah[mt], bl8[f]);
                mma_bf16(acc[mt][f], al[mt], bh[f]);
            }
        __syncthreads();
    }

#pragma unroll
    for (int f = 0; f < 8; f++) {
        int col = n0 + wn * 64 + f * 8 + tig * 2;
        float bl0 = bias[col], bl1 = bias[col + 1];
#pragma unroll
        for (int mt = 0; mt < 2; mt++) {
            int mr0 = m0 + wm * 32 + mt * 16 + g;
            int bb = mr0 >> 10, t = mr0 & 1023;
            float2 v0 = {acc[mt][f][0] + bl0, acc[mt][f][1] + bl1};
            *(float2*)&g_xw[((size_t)t * BB + bb) * G4 + col] = v0;
            int mr1 = mr0 + 8;
            bb = mr1 >> 10; t = mr1 & 1023;
            float2 v1 = {acc[mt][f][2] + bl0, acc[mt][f][3] + bl1};
            *(float2*)&g_xw[((size_t)t * BB + bb) * G4 + col] = v1;
        }
    }
}

// ---------------- kernel 2: persistent recurrence, bf16-split TC GEMM --------
// Per CTA step: z[32][16] = h[32][512] @ WhSlice[512][16], K split over 8 warps
// (K=64 each), 4-product bf16-split mma (hi,lo x hi,lo) -> exact to ~2^-18.
// h stored as bf16 hi/lo pairs (4B/value, same traffic as fp32); writers split.
// smem rows padded to 520 bf16 (1040B = 65 x 16B units -> ldmatrix conflict-free).
#define WHP      520
#define OFF_WHHI 0
#define OFF_WHLO 16640
#define OFF_HHI  33280
#define OFF_HLO  66560
#define OFF_RED  99840
#define SMEM_REC 118272
__global__ __launch_bounds__(256, 1) void lstm_rec_kernel(
    const float* __restrict__ Wh, float* __restrict__ out)
{
    extern __shared__ char smem[];
    unsigned sb = (unsigned)__cvta_generic_to_shared(smem);
    __nv_bfloat16* whhi = (__nv_bfloat16*)(smem + OFF_WHHI);
    __nv_bfloat16* whlo = (__nv_bfloat16*)(smem + OFF_WHLO);
    float*         red_s = (float*)(smem + OFF_RED);   // [8][32][18]

    int tid = threadIdx.x;
    int j0  = blockIdx.x * 4;

    // split Wh slice into smem: row c = gate*4+jj (16 rows x 512 k)
    for (int idx = tid; idx < 16 * 512; idx += 256) {
        int k = idx >> 4, c = idx & 15;
        float wv = Wh[(size_t)k * G4 + (c >> 2) * HH + j0 + (c & 3)];
        __nv_bfloat16 hi = __float2bfloat16(wv);
        __nv_bfloat16 lo = __float2bfloat16(wv - __bfloat162float(hi));
        whhi[c * WHP + k] = hi;
        whlo[c * WHP + k] = lo;
    }

    int w    = tid >> 5;
    int lane = tid & 31;
    int g    = lane >> 2, tig = lane & 3;

    int a_row_off = ((lane >> 3) & 1) * 8 + (lane & 7);
    int a_k_off   = ((lane >> 4) & 1) * 16;
    int b_row_off = ((lane >> 4) & 1) * 8 + (lane & 7);
    int b_k_off   = ((lane >> 3) & 1) * 16;

    // update role (tid < 128): (batch ub, h-col j0+uj)
    int ub = tid >> 2, uj = tid & 3;
    float creg = 0.f;
    float* outp = out + ((size_t)ub * TT) * HH + j0 + uj;

    unsigned bar_target = NCTA;
    __syncthreads();

    float px0 = 0.f, px1 = 0.f, px2 = 0.f, px3 = 0.f;
    if (tid < 128) {
        const float* xr = g_xw + (size_t)ub * G4 + j0 + uj;
        px0 = __ldg(xr);        px1 = __ldg(xr + 512);
        px2 = __ldg(xr + 1024); px3 = __ldg(xr + 1536);
    }

    for (int t = 0; t < TT; t++) {
        int buf = t & 1;
        // per-warp h load: k-slice [64w, 64w+64), both splits, 2 commit groups
        {
#pragma unroll
            for (int grp = 0; grp < 2; grp++) {
#pragma unroll
                for (int sp = 0; sp < 2; sp++) {
                    const __nv_bfloat16* gsrc = sp ? g_hlo[buf] : g_hhi[buf];
                    unsigned hb = sb + (sp ? OFF_HLO : OFF_HHI);
#pragma unroll
                    for (int i = 0; i < 4; i++) {
                        int v  = i * 32 + lane;          // 0..127
                        int r  = v >> 2, c4 = v & 3;
                        int ko = 64 * w + grp * 32 + c4 * 8;
                        asm volatile("cp.async.cg.shared.global [%0], [%1], 16;"
                                     :: "r"(hb + (unsigned)(r * 1040 + ko * 2)),
                                        "l"(gsrc + (size_t)r * HH + ko)
                                     : "memory");
                    }
                }
                asm volatile("cp.async.commit_group;");
            }
        }

        float acc[2][2][4];
#pragma unroll
        for (int mt = 0; mt < 2; mt++)
#pragma unroll
            for (int nt = 0; nt < 2; nt++)
#pragma unroll
                for (int q = 0; q < 4; q++) acc[mt][nt][q] = 0.f;

#pragma unroll
        for (int grp = 0; grp < 2; grp++) {
            if (grp == 0) { asm volatile("cp.async.wait_group 1;" ::: "memory"); }
            else          { asm volatile("cp.async.wait_group 0;" ::: "memory"); }
            __syncwarp();
#pragma unroll
            for (int ktl = 0; ktl < 2; ktl++) {
                int kb = 128 * w + grp * 64 + ktl * 32;   // byte offset of 16-k tile
                unsigned ahi[2][4], alo[2][4];
#pragma unroll
                for (int mt = 0; mt < 2; mt++) {
                    unsigned rowb = (mt * 16 + a_row_off) * 1040 + kb + a_k_off;
                    ldm4(ahi[mt], sb + OFF_HHI + rowb);
                    ldm4(alo[mt], sb + OFF_HLO + rowb);
                }
                unsigned r4[4], bh[2][2], bl[2][2];
                unsigned rowbB = b_row_off * 1040 + kb + b_k_off;
                ldm4(r4, sb + OFF_WHHI + rowbB);
                bh[0][0] = r4[0]; bh[0][1] = r4[1];
                bh[1][0] = r4[2]; bh[1][1] = r4[3];
                ldm4(r4, sb + OFF_WHLO + rowbB);
                bl[0][0] = r4[0]; bl[0][1] = r4[1];
                bl[1][0] = r4[2]; bl[1][1] = r4[3];
#pragma unroll
                for (int mt = 0; mt < 2; mt++)
#pragma unroll
                    for (int nt = 0; nt < 2; nt++) {
                        mma_bf16(acc[mt][nt], ahi[mt], bh[nt]);
                        mma_bf16(acc[mt][nt], ahi[mt], bl[nt]);
                        mma_bf16(acc[mt][nt], alo[mt], bh[nt]);
                        mma_bf16(acc[mt][nt], alo[mt], bl[nt]);
                    }
            }
        }

        // store warp partials: red_s[w][row=b][col=c], rows from C-fragment map
        {
            float* rw = red_s + w * 32 * 18;
#pragma unroll
            for (int mt = 0; mt < 2; mt++)
#pragma unroll
                for (int nt = 0; nt < 2; nt++) {
                    int col = nt * 8 + tig * 2;
                    float2 v0 = {acc[mt][nt][0], acc[mt][nt][1]};
                    float2 v1 = {acc[mt][nt][2], acc[mt][nt][3]};
                    *(float2*)&rw[(mt * 16 + g) * 18 + col]     = v0;
                    *(float2*)&rw[(mt * 16 + g + 8) * 18 + col] = v1;
                }
        }
        __syncthreads();

        // update threads: sum 8 warp partials, gates at cols uj, uj+4, uj+8, uj+12
        if (tid < 128) {
            float zi = 0.f, zf = 0.f, zg = 0.f, zo = 0.f;
#pragma unroll
            for (int w8 = 0; w8 < 8; w8++) {
                const float* r = red_s + (w8 * 32 + ub) * 18;
                zi += r[uj];      zf += r[4 + uj];
                zg += r[8 + uj];  zo += r[12 + uj];
            }
            zi += px0; zf += px1; zg += px2; zo += px3;
            float ig = fsig(zi);
            float fg = fsig(zf);
            float gg = ftanh(zg);
            float og = fsig(zo);
            float cn = fg * creg + ig * gg;
            creg = cn;
            float hn = og * ftanh(cn);
            __nv_bfloat16 hi = __float2bfloat16(hn);
            __nv_bfloat16 lo = __float2bfloat16(hn - __bfloat162float(hi));
            int nb = (t + 1) & 1;
            g_hhi[nb][(size_t)ub * HH + j0 + uj] = hi;
            g_hlo[nb][(size_t)ub * HH + j0 + uj] = lo;
            outp[(size_t)t * HH] = hn;

            // prefetch next step's px under the barrier
            int tn = (t + 1 < TT) ? t + 1 : t;
            const float* xr = g_xw + ((size_t)tn * BB + ub) * G4 + j0 + uj;
            px0 = __ldg(xr);        px1 = __ldg(xr + 512);
            px2 = __ldg(xr + 1024); px3 = __ldg(xr + 1536);
        }
        __syncthreads();

        if (tid == 0) {
            asm volatile("red.release.gpu.global.add.u32 [%0], %1;"
                         :: "l"(&g_bar), "r"(1u) : "memory");
            unsigned v;
            do {
                asm volatile("ld.acquire.gpu.global.u32 %0, [%1];"
                             : "=r"(v) : "l"(&g_bar) : "memory");
            } while (v < bar_target);
        }
        bar_target += NCTA;
        __syncthreads();
    }
}

// ---------------- kernel 3: gather final states ------------------------------
__global__ void gather_final_kernel(const int* __restrict__ lenraw, float* __restrict__ out) {
    __shared__ int is32;
    if (threadIdx.x == 0) {
        const long long* l64 = (const long long*)lenraw;
        int bad = 0;
        for (int b = 0; b < 16; b++) {
            long long v = l64[b];
            if (v < 0 || v > (long long)TT) bad = 1;
        }
        is32 = bad;
    }
    __syncthreads();
    int idx = blockIdx.x * blockDim.x + threadIdx.x;
    if (idx >= BB * HH) return;
    int b = idx >> 9, j = idx & 511;
    long long len = is32 ? (long long)lenraw[b] : ((const long long*)lenraw)[b];
    long long tt = len > 0 ? len - 1 : 0;
    out[(size_t)BB * TT * HH + idx] = out[((size_t)b * TT + tt) * HH + j];
}

// ---------------- launch ------------------------------------------------------
extern "C" void kernel_launch(void* const* d_in, const int* in_sizes, int n_in,
                              void* d_out, int out_size) {
    const float* X    = (const float*)d_in[0];
    const int*   lenr = (const int*)  d_in[1];
    const float* Wx   = (const float*)d_in[2];
    const float* Wh   = (const float*)d_in[3];
    const float* bias = (const float*)d_in[4];
    float* out = (float*)d_out;

    int smem_xw = 2 * XW_STAGE;                              // 49,152 B

    cudaFuncSetAttribute(lstm_rec_kernel,
                         cudaFuncAttributeMaxDynamicSharedMemorySize, SMEM_REC);
    cudaFuncSetAttribute(lstm_rec_kernel,
                         cudaFuncAttributePreferredSharedMemoryCarveout, 100);
    cudaFuncSetAttribute(gemm_xw_tc_kernel,
                         cudaFuncAttributeMaxDynamicSharedMemorySize, smem_xw);

    reset_kernel<<<64, 256>>>();
    conv_all_kernel<<<20480, 256>>>(X, Wx);
    gemm_xw_tc_kernel<<<dim3(16, 256), 256, smem_xw>>>(bias);
    lstm_rec_kernel<<<NCTA, 256, SMEM_REC>>>(Wh, out);       // launch slot #4
    gather_final_kernel<<<64, 256>>>(lenr, out);
}